// round 9
// baseline (speedup 1.0000x reference)
#include <cuda_runtime.h>
#include <math.h>

#define B_ 16
#define N_ 16384
#define D_ 64
#define K_ 64
#define T_ 128            // points per tile
#define SPLIT_ 16         // CTAs per batch
#define TILES_ (N_ / SPLIT_ / T_)   // 8
#define XST_ 68           // padded row stride (floats) for xs/qs
#define SLOT_ (K_ + 2 * K_ * D_)    // 8256 floats per partial slot

typedef unsigned long long u64;

// ---- packed f32x2 helpers (sm_100+ PTX) ----
__device__ __forceinline__ u64 pk2(float a, float b) {
    u64 r; asm("mov.b64 %0, {%1, %2};" : "=l"(r) : "f"(a), "f"(b)); return r;
}
__device__ __forceinline__ void up2(float& a, float& b, u64 v) {
    asm("mov.b64 {%0, %1}, %2;" : "=f"(a), "=f"(b) : "l"(v));
}
__device__ __forceinline__ u64 fma2(u64 a, u64 b, u64 c) {
    u64 r; asm("fma.rn.f32x2 %0, %1, %2, %3;" : "=l"(r) : "l"(a), "l"(b), "l"(c)); return r;
}
__device__ __forceinline__ u64 mul2(u64 a, u64 b) {
    u64 r; asm("mul.rn.f32x2 %0, %1, %2;" : "=l"(r) : "l"(a), "l"(b)); return r;
}
__device__ __forceinline__ u64 add2(u64 a, u64 b) {
    u64 r; asm("add.rn.f32x2 %0, %1, %2;" : "=l"(r) : "l"(a), "l"(b)); return r;
}

// Partial accumulators: one slot per (batch, split). Fully written each launch.
__device__ __align__(16) float g_part[(size_t)B_ * SPLIT_ * SLOT_];

// Dynamic shared layout (float offsets)
#define SM_IVT 0                          // -0.5/var, transposed [d][k]   K*D
#define SM_AAT (K_ * D_)                  // mu/var, transposed [d][k]     K*D
#define SM_CC  (2 * K_ * D_)              // per-k log const               K
#define SM_XS  (2 * K_ * D_ + K_)        // x tile  [T][XST]
#define SM_QS  (SM_XS + T_ * XST_)       // Q tile  [T][XST]
#define SM_FLOATS (SM_QS + T_ * XST_)    // 25664 floats = 102656 B

__global__ __launch_bounds__(256, 2) void fv_main(
    const float* __restrict__ x, const float* __restrict__ pi,
    const float* __restrict__ mu, const float* __restrict__ var)
{
    extern __shared__ float sm[];
    float* ivhT = sm + SM_IVT;
    float* aaT  = sm + SM_AAT;
    float* cc   = sm + SM_CC;
    float* xs   = sm + SM_XS;
    float* qs   = sm + SM_QS;

    const int tid = threadIdx.x;
    const int b = blockIdx.y;
    const int s = blockIdx.x;

    // ---- stage transposed params in shared ----
    for (int i = tid; i < K_ * D_; i += 256) {
        int k = i >> 6, d = i & 63;
        float v = var[i];
        float iv = 1.0f / v;
        ivhT[d * K_ + k] = -0.5f * iv;
        aaT[d * K_ + k]  = mu[i] * iv;
    }
    if (tid < K_) {
        float acc = 0.0f;
        for (int d = 0; d < D_; ++d) {
            float v = var[tid * D_ + d];
            float m = mu[tid * D_ + d];
            acc += logf(v) + m * m / v;
        }
        cc[tid] = logf(pi[tid]) - 0.5f * ((float)D_ * 1.83787706640934548356f + acc);
    }
    // first tile's __syncthreads publishes params

    // phase-1 thread map: pg (point group of 4), kg (k group of 8)
    const int pg = tid >> 3;
    const int kg = tid & 7;
    // phase-2 thread map: tk (k group of 4), td (d group of 4)
    const int tk = tid >> 4;
    const int td = tid & 15;

    u64 accX[4][2]  = {};   // Q_x  : 4 k-rows x 2 d-pairs
    u64 accX2[4][2] = {};   // Q_x2
    u64 qacc[4]     = {};   // per-thread Q column sums (4 k-pairs)

    const int n_base = s * (N_ / SPLIT_);

    for (int tile = 0; tile < TILES_; ++tile) {
        const int n0 = n_base + tile * T_;
        // ---- coalesced load of x tile ----
        const float4* xg = (const float4*)(x + ((size_t)b * N_ + n0) * (size_t)D_);
        #pragma unroll
        for (int ii = 0; ii < 8; ++ii) {
            int i = tid + ii * 256;
            float4 v = xg[i];
            int row = i >> 4, c4 = i & 15;
            *(float4*)(xs + row * XST_ + c4 * 4) = v;
        }
        __syncthreads();

        // ---- phase 1: logits via register-blocked packed GEMM ----
        u64 lp[4][4];
        {
            const u64* cc2 = (const u64*)(cc + kg * 8);
            u64 c0 = cc2[0], c1 = cc2[1], c2 = cc2[2], c3 = cc2[3];
            #pragma unroll
            for (int p = 0; p < 4; ++p) { lp[p][0]=c0; lp[p][1]=c1; lp[p][2]=c2; lp[p][3]=c3; }
        }
        #pragma unroll 4
        for (int d0 = 0; d0 < D_; d0 += 4) {
            float xvv[4][4];
            #pragma unroll
            for (int p = 0; p < 4; ++p) {
                float4 t = *(const float4*)(xs + (pg * 4 + p) * XST_ + d0);
                xvv[p][0]=t.x; xvv[p][1]=t.y; xvv[p][2]=t.z; xvv[p][3]=t.w;
            }
            #pragma unroll
            for (int dd = 0; dd < 4; ++dd) {
                const int d = d0 + dd;
                ulonglong2 ih = *(const ulonglong2*)(ivhT + d * K_ + kg * 8);
                ulonglong2 ih2 = *(const ulonglong2*)(ivhT + d * K_ + kg * 8 + 4);
                ulonglong2 av = *(const ulonglong2*)(aaT  + d * K_ + kg * 8);
                ulonglong2 av2 = *(const ulonglong2*)(aaT  + d * K_ + kg * 8 + 4);
                #pragma unroll
                for (int p = 0; p < 4; ++p) {
                    float xd = xvv[p][dd];
                    u64 xp  = pk2(xd, xd);
                    u64 x2p = mul2(xp, xp);
                    lp[p][0] = fma2(x2p, ih.x,  lp[p][0]);
                    lp[p][1] = fma2(x2p, ih.y,  lp[p][1]);
                    lp[p][2] = fma2(x2p, ih2.x, lp[p][2]);
                    lp[p][3] = fma2(x2p, ih2.y, lp[p][3]);
                    lp[p][0] = fma2(xp,  av.x,  lp[p][0]);
                    lp[p][1] = fma2(xp,  av.y,  lp[p][1]);
                    lp[p][2] = fma2(xp,  av2.x, lp[p][2]);
                    lp[p][3] = fma2(xp,  av2.y, lp[p][3]);
                }
            }
        }

        // ---- softmax over K (8 local k x 8 lanes) ----
        #pragma unroll
        for (int p = 0; p < 4; ++p) {
            float q[8];
            up2(q[0], q[1], lp[p][0]); up2(q[2], q[3], lp[p][1]);
            up2(q[4], q[5], lp[p][2]); up2(q[6], q[7], lp[p][3]);
            float mx = q[0];
            #pragma unroll
            for (int j = 1; j < 8; ++j) mx = fmaxf(mx, q[j]);
            mx = fmaxf(mx, __shfl_xor_sync(0xffffffffu, mx, 1));
            mx = fmaxf(mx, __shfl_xor_sync(0xffffffffu, mx, 2));
            mx = fmaxf(mx, __shfl_xor_sync(0xffffffffu, mx, 4));
            float sum = 0.0f;
            #pragma unroll
            for (int j = 0; j < 8; ++j) { q[j] = __expf(q[j] - mx); sum += q[j]; }
            sum += __shfl_xor_sync(0xffffffffu, sum, 1);
            sum += __shfl_xor_sync(0xffffffffu, sum, 2);
            sum += __shfl_xor_sync(0xffffffffu, sum, 4);
            float inv = __fdividef(1.0f, sum);
            u64 qp0 = pk2(q[0] * inv, q[1] * inv);
            u64 qp1 = pk2(q[2] * inv, q[3] * inv);
            u64 qp2 = pk2(q[4] * inv, q[5] * inv);
            u64 qp3 = pk2(q[6] * inv, q[7] * inv);
            qacc[0] = add2(qacc[0], qp0); qacc[1] = add2(qacc[1], qp1);
            qacc[2] = add2(qacc[2], qp2); qacc[3] = add2(qacc[3], qp3);
            ulonglong2* qdst = (ulonglong2*)(qs + (pg * 4 + p) * XST_ + kg * 8);
            qdst[0] = make_ulonglong2(qp0, qp1);
            qdst[1] = make_ulonglong2(qp2, qp3);
        }
        __syncthreads();

        // ---- phase 2: rank-T packed update of Q_x / Q_x2 ----
        #pragma unroll 4
        for (int n = 0; n < T_; ++n) {
            ulonglong2 qv = *(const ulonglong2*)(qs + n * XST_ + tk * 4);
            ulonglong2 xv = *(const ulonglong2*)(xs + n * XST_ + td * 4);
            u64 xp0 = xv.x, xp1 = xv.y;
            u64 x2p0 = mul2(xp0, xp0);
            u64 x2p1 = mul2(xp1, xp1);
            float q0, q1, q2, q3;
            up2(q0, q1, qv.x); up2(q2, q3, qv.y);
            u64 qq0 = pk2(q0, q0), qq1 = pk2(q1, q1);
            u64 qq2 = pk2(q2, q2), qq3 = pk2(q3, q3);
            accX[0][0] = fma2(qq0, xp0, accX[0][0]); accX[0][1] = fma2(qq0, xp1, accX[0][1]);
            accX[1][0] = fma2(qq1, xp0, accX[1][0]); accX[1][1] = fma2(qq1, xp1, accX[1][1]);
            accX[2][0] = fma2(qq2, xp0, accX[2][0]); accX[2][1] = fma2(qq2, xp1, accX[2][1]);
            accX[3][0] = fma2(qq3, xp0, accX[3][0]); accX[3][1] = fma2(qq3, xp1, accX[3][1]);
            accX2[0][0] = fma2(qq0, x2p0, accX2[0][0]); accX2[0][1] = fma2(qq0, x2p1, accX2[0][1]);
            accX2[1][0] = fma2(qq1, x2p0, accX2[1][0]); accX2[1][1] = fma2(qq1, x2p1, accX2[1][1]);
            accX2[2][0] = fma2(qq2, x2p0, accX2[2][0]); accX2[2][1] = fma2(qq2, x2p1, accX2[2][1]);
            accX2[3][0] = fma2(qq3, x2p0, accX2[3][0]); accX2[3][1] = fma2(qq3, x2p1, accX2[3][1]);
        }
        __syncthreads();
    }

    // ---- reduce qacc across pg groups (reuse xs as scratch) ----
    float* part = xs;   // [32][64]
    #pragma unroll
    for (int j = 0; j < 4; ++j)
        *(u64*)(part + pg * K_ + kg * 8 + 2 * j) = qacc[j];
    __syncthreads();

    float* slot = g_part + ((size_t)b * SPLIT_ + s) * SLOT_;
    if (tid < K_) {
        float qsum = 0.0f;
        #pragma unroll 8
        for (int r = 0; r < 32; ++r) qsum += part[r * K_ + tid];
        slot[tid] = qsum;
    }
    float* qxs  = slot + K_;
    float* qx2s = slot + K_ + K_ * D_;
    #pragma unroll
    for (int i = 0; i < 4; ++i) {
        int k = tk * 4 + i;
        *(ulonglong2*)(qxs  + k * D_ + td * 4) = make_ulonglong2(accX[i][0],  accX[i][1]);
        *(ulonglong2*)(qx2s + k * D_ + td * 4) = make_ulonglong2(accX2[i][0], accX2[i][1]);
    }
}

__global__ __launch_bounds__(256) void fv_final(
    const float* __restrict__ pi, const float* __restrict__ mu,
    const float* __restrict__ var, float* __restrict__ out)
{
    const int b = blockIdx.x;
    const int seg = blockIdx.y;      // 0..7, each handles 512 of K*D
    const int tid = threadIdx.x;
    __shared__ float qsum_s[K_];
    const float* base = g_part + (size_t)b * SPLIT_ * SLOT_;
    const float inv_n = 1.0f / (float)N_;

    if (tid < K_) {
        float ssum = 0.0f;
        #pragma unroll
        for (int t = 0; t < SPLIT_; ++t) ssum += base[(size_t)t * SLOT_ + tid];
        ssum *= inv_n;
        qsum_s[tid] = ssum;
        if (seg == 0) out[(size_t)b * SLOT_ + tid] = ssum - pi[tid];   // d_pi
    }
    __syncthreads();

    #pragma unroll
    for (int ii = 0; ii < 2; ++ii) {
        int idx = seg * 512 + ii * 256 + tid;
        float qx = 0.0f, qx2 = 0.0f;
        #pragma unroll
        for (int t = 0; t < SPLIT_; ++t) {
            const float* sl = base + (size_t)t * SLOT_;
            qx  += sl[K_ + idx];
            qx2 += sl[K_ + K_ * D_ + idx];
        }
        qx *= inv_n; qx2 *= inv_n;
        int k = idx >> 6;
        float m = mu[idx];
        float v = var[idx];
        float qsv = qsum_s[k];
        out[(size_t)b * SLOT_ + K_ + idx] = qx - qsv * m;                     // d_mu
        out[(size_t)b * SLOT_ + K_ + K_ * D_ + idx] =
            -qx2 - qsv * m * m + qsv * v + 2.0f * qx * m;                     // d_sigma
    }
}

extern "C" void kernel_launch(void* const* d_in, const int* in_sizes, int n_in,
                              void* d_out, int out_size)
{
    const float* x   = (const float*)d_in[0];
    const float* pi  = (const float*)d_in[1];
    const float* mu  = (const float*)d_in[2];
    const float* var = (const float*)d_in[3];
    float* out = (float*)d_out;

    size_t smem = (size_t)SM_FLOATS * sizeof(float);  // 102,656 bytes -> occ 2
    cudaFuncSetAttribute(fv_main, cudaFuncAttributeMaxDynamicSharedMemorySize, (int)smem);

    dim3 grid(SPLIT_, B_);
    fv_main<<<grid, 256, smem>>>(x, pi, mu, var);
    dim3 g2(B_, 8);
    fv_final<<<g2, 256>>>(pi, mu, var, out);
}

// round 11
// speedup vs baseline: 1.0535x; 1.0535x over previous
#include <cuda_runtime.h>
#include <math.h>

#define B_ 16
#define N_ 16384
#define D_ 64
#define K_ 64
#define T_ 128            // points per tile
#define SPLIT_ 16         // CTAs per batch
#define TILES_ (N_ / SPLIT_ / T_)   // 8
#define XST_ 68           // padded row stride (floats) for xs/qs
#define SLOT_ (K_ + 2 * K_ * D_)    // 8256 floats per partial slot

typedef unsigned long long u64;

// ---- packed f32x2 helpers (sm_100+ PTX) ----
__device__ __forceinline__ u64 pk2(float a, float b) {
    u64 r; asm("mov.b64 %0, {%1, %2};" : "=l"(r) : "f"(a), "f"(b)); return r;
}
__device__ __forceinline__ void up2(float& a, float& b, u64 v) {
    asm("mov.b64 {%0, %1}, %2;" : "=f"(a), "=f"(b) : "l"(v));
}
__device__ __forceinline__ u64 fma2(u64 a, u64 b, u64 c) {
    u64 r; asm("fma.rn.f32x2 %0, %1, %2, %3;" : "=l"(r) : "l"(a), "l"(b), "l"(c)); return r;
}
__device__ __forceinline__ u64 mul2(u64 a, u64 b) {
    u64 r; asm("mul.rn.f32x2 %0, %1, %2;" : "=l"(r) : "l"(a), "l"(b)); return r;
}
__device__ __forceinline__ u64 add2(u64 a, u64 b) {
    u64 r; asm("add.rn.f32x2 %0, %1, %2;" : "=l"(r) : "l"(a), "l"(b)); return r;
}

// Partial accumulators: one slot per (batch, split). Fully written each launch.
__device__ __align__(16) float g_part[(size_t)B_ * SPLIT_ * SLOT_];

// Dynamic shared layout (float offsets)
#define SM_IVT 0                          // -0.5/var, transposed [d][k]   K*D
#define SM_AAT (K_ * D_)                  // mu/var, transposed [d][k]     K*D
#define SM_CC  (2 * K_ * D_)              // per-k log const               K
#define SM_XS  (2 * K_ * D_ + K_)        // x tile  [T][XST]
#define SM_QS  (SM_XS + T_ * XST_)       // Q tile  [T][XST]
#define SM_FLOATS (SM_QS + T_ * XST_)    // 25664 floats = 102656 B

__global__ __launch_bounds__(256, 2) void fv_main(
    const float* __restrict__ x, const float* __restrict__ pi,
    const float* __restrict__ mu, const float* __restrict__ var)
{
    extern __shared__ float sm[];
    float* ivhT = sm + SM_IVT;
    float* aaT  = sm + SM_AAT;
    float* cc   = sm + SM_CC;
    float* xs   = sm + SM_XS;
    float* qs   = sm + SM_QS;

    const int tid = threadIdx.x;
    const int b = blockIdx.y;
    const int s = blockIdx.x;

    // ---- stage transposed params in shared ----
    for (int i = tid; i < K_ * D_; i += 256) {
        int k = i >> 6, d = i & 63;
        float v = var[i];
        float iv = 1.0f / v;
        ivhT[d * K_ + k] = -0.5f * iv;
        aaT[d * K_ + k]  = mu[i] * iv;
    }
    if (tid < K_) {
        float acc = 0.0f;
        for (int d = 0; d < D_; ++d) {
            float v = var[tid * D_ + d];
            float m = mu[tid * D_ + d];
            acc += logf(v) + m * m / v;
        }
        cc[tid] = logf(pi[tid]) - 0.5f * ((float)D_ * 1.83787706640934548356f + acc);
    }
    // first tile's __syncthreads publishes params

    // phase-1 thread map: pg (point group of 4), kg (k group of 8)
    const int pg = tid >> 3;
    const int kg = tid & 7;
    // phase-2 thread map: tk (k group of 4), td (d group of 4)
    const int tk = tid >> 4;
    const int td = tid & 15;

    u64 accX[4][2]  = {};   // Q_x  : 4 k-rows x 2 d-pairs
    u64 accX2[4][2] = {};   // Q_x2
    u64 qacc[4]     = {};   // per-thread Q column sums (4 k-pairs)

    const int n_base = s * (N_ / SPLIT_);

    for (int tile = 0; tile < TILES_; ++tile) {
        const int n0 = n_base + tile * T_;
        // ---- coalesced load of x tile ----
        const float4* xg = (const float4*)(x + ((size_t)b * N_ + n0) * (size_t)D_);
        #pragma unroll
        for (int ii = 0; ii < 8; ++ii) {
            int i = tid + ii * 256;
            float4 v = xg[i];
            int row = i >> 4, c4 = i & 15;
            *(float4*)(xs + row * XST_ + c4 * 4) = v;
        }
        __syncthreads();

        // ---- phase 1: logits via register-blocked packed GEMM ----
        u64 lp[4][4];
        {
            const u64* cc2 = (const u64*)(cc + kg * 8);
            u64 c0 = cc2[0], c1 = cc2[1], c2 = cc2[2], c3 = cc2[3];
            #pragma unroll
            for (int p = 0; p < 4; ++p) { lp[p][0]=c0; lp[p][1]=c1; lp[p][2]=c2; lp[p][3]=c3; }
        }
        #pragma unroll 4
        for (int d0 = 0; d0 < D_; d0 += 4) {
            float xvv[4][4];
            #pragma unroll
            for (int p = 0; p < 4; ++p) {
                float4 t = *(const float4*)(xs + (pg * 4 + p) * XST_ + d0);
                xvv[p][0]=t.x; xvv[p][1]=t.y; xvv[p][2]=t.z; xvv[p][3]=t.w;
            }
            #pragma unroll
            for (int dd = 0; dd < 4; ++dd) {
                const int d = d0 + dd;
                ulonglong2 ih = *(const ulonglong2*)(ivhT + d * K_ + kg * 8);
                ulonglong2 ih2 = *(const ulonglong2*)(ivhT + d * K_ + kg * 8 + 4);
                ulonglong2 av = *(const ulonglong2*)(aaT  + d * K_ + kg * 8);
                ulonglong2 av2 = *(const ulonglong2*)(aaT  + d * K_ + kg * 8 + 4);
                #pragma unroll
                for (int p = 0; p < 4; ++p) {
                    float xd = xvv[p][dd];
                    u64 xp  = pk2(xd, xd);
                    u64 x2p = mul2(xp, xp);
                    lp[p][0] = fma2(x2p, ih.x,  lp[p][0]);
                    lp[p][1] = fma2(x2p, ih.y,  lp[p][1]);
                    lp[p][2] = fma2(x2p, ih2.x, lp[p][2]);
                    lp[p][3] = fma2(x2p, ih2.y, lp[p][3]);
                    lp[p][0] = fma2(xp,  av.x,  lp[p][0]);
                    lp[p][1] = fma2(xp,  av.y,  lp[p][1]);
                    lp[p][2] = fma2(xp,  av2.x, lp[p][2]);
                    lp[p][3] = fma2(xp,  av2.y, lp[p][3]);
                }
            }
        }

        // ---- softmax over K (8 local k x 8 lanes) ----
        #pragma unroll
        for (int p = 0; p < 4; ++p) {
            float q[8];
            up2(q[0], q[1], lp[p][0]); up2(q[2], q[3], lp[p][1]);
            up2(q[4], q[5], lp[p][2]); up2(q[6], q[7], lp[p][3]);
            float mx = q[0];
            #pragma unroll
            for (int j = 1; j < 8; ++j) mx = fmaxf(mx, q[j]);
            mx = fmaxf(mx, __shfl_xor_sync(0xffffffffu, mx, 1));
            mx = fmaxf(mx, __shfl_xor_sync(0xffffffffu, mx, 2));
            mx = fmaxf(mx, __shfl_xor_sync(0xffffffffu, mx, 4));
            float sum = 0.0f;
            #pragma unroll
            for (int j = 0; j < 8; ++j) { q[j] = __expf(q[j] - mx); sum += q[j]; }
            sum += __shfl_xor_sync(0xffffffffu, sum, 1);
            sum += __shfl_xor_sync(0xffffffffu, sum, 2);
            sum += __shfl_xor_sync(0xffffffffu, sum, 4);
            float inv = __fdividef(1.0f, sum);
            u64 qp0 = pk2(q[0] * inv, q[1] * inv);
            u64 qp1 = pk2(q[2] * inv, q[3] * inv);
            u64 qp2 = pk2(q[4] * inv, q[5] * inv);
            u64 qp3 = pk2(q[6] * inv, q[7] * inv);
            qacc[0] = add2(qacc[0], qp0); qacc[1] = add2(qacc[1], qp1);
            qacc[2] = add2(qacc[2], qp2); qacc[3] = add2(qacc[3], qp3);
            ulonglong2* qdst = (ulonglong2*)(qs + (pg * 4 + p) * XST_ + kg * 8);
            qdst[0] = make_ulonglong2(qp0, qp1);
            qdst[1] = make_ulonglong2(qp2, qp3);
        }
        __syncthreads();

        // ---- phase 2: rank-T packed update of Q_x / Q_x2 ----
        #pragma unroll 4
        for (int n = 0; n < T_; ++n) {
            ulonglong2 qv = *(const ulonglong2*)(qs + n * XST_ + tk * 4);
            ulonglong2 xv = *(const ulonglong2*)(xs + n * XST_ + td * 4);
            u64 xp0 = xv.x, xp1 = xv.y;
            u64 x2p0 = mul2(xp0, xp0);
            u64 x2p1 = mul2(xp1, xp1);
            float q0, q1, q2, q3;
            up2(q0, q1, qv.x); up2(q2, q3, qv.y);
            u64 qq0 = pk2(q0, q0), qq1 = pk2(q1, q1);
            u64 qq2 = pk2(q2, q2), qq3 = pk2(q3, q3);
            accX[0][0] = fma2(qq0, xp0, accX[0][0]); accX[0][1] = fma2(qq0, xp1, accX[0][1]);
            accX[1][0] = fma2(qq1, xp0, accX[1][0]); accX[1][1] = fma2(qq1, xp1, accX[1][1]);
            accX[2][0] = fma2(qq2, xp0, accX[2][0]); accX[2][1] = fma2(qq2, xp1, accX[2][1]);
            accX[3][0] = fma2(qq3, xp0, accX[3][0]); accX[3][1] = fma2(qq3, xp1, accX[3][1]);
            accX2[0][0] = fma2(qq0, x2p0, accX2[0][0]); accX2[0][1] = fma2(qq0, x2p1, accX2[0][1]);
            accX2[1][0] = fma2(qq1, x2p0, accX2[1][0]); accX2[1][1] = fma2(qq1, x2p1, accX2[1][1]);
            accX2[2][0] = fma2(qq2, x2p0, accX2[2][0]); accX2[2][1] = fma2(qq2, x2p1, accX2[2][1]);
            accX2[3][0] = fma2(qq3, x2p0, accX2[3][0]); accX2[3][1] = fma2(qq3, x2p1, accX2[3][1]);
        }
        __syncthreads();
    }

    // ---- reduce qacc across pg groups (reuse xs as scratch) ----
    float* part = xs;   // [32][64]
    #pragma unroll
    for (int j = 0; j < 4; ++j)
        *(u64*)(part + pg * K_ + kg * 8 + 2 * j) = qacc[j];
    __syncthreads();

    float* slot = g_part + ((size_t)b * SPLIT_ + s) * SLOT_;
    if (tid < K_) {
        float qsum = 0.0f;
        #pragma unroll 8
        for (int r = 0; r < 32; ++r) qsum += part[r * K_ + tid];
        slot[tid] = qsum;
    }
    float* qxs  = slot + K_;
    float* qx2s = slot + K_ + K_ * D_;
    #pragma unroll
    for (int i = 0; i < 4; ++i) {
        int k = tk * 4 + i;
        *(ulonglong2*)(qxs  + k * D_ + td * 4) = make_ulonglong2(accX[i][0],  accX[i][1]);
        *(ulonglong2*)(qx2s + k * D_ + td * 4) = make_ulonglong2(accX2[i][0], accX2[i][1]);
    }
}

__global__ __launch_bounds__(256) void fv_final(
    const float* __restrict__ pi, const float* __restrict__ mu,
    const float* __restrict__ var, float* __restrict__ out)
{
    const int b = blockIdx.x;
    const int seg = blockIdx.y;      // 0..7, each handles 512 of K*D
    const int tid = threadIdx.x;
    __shared__ float qsum_s[K_];
    const float* base = g_part + (size_t)b * SPLIT_ * SLOT_;
    const float inv_n = 1.0f / (float)N_;

    if (tid < K_) {
        float ssum = 0.0f;
        #pragma unroll
        for (int t = 0; t < SPLIT_; ++t) ssum += base[(size_t)t * SLOT_ + tid];
        ssum *= inv_n;
        qsum_s[tid] = ssum;
        if (seg == 0) out[(size_t)b * SLOT_ + tid] = ssum - pi[tid];   // d_pi
    }
    __syncthreads();

    #pragma unroll
    for (int ii = 0; ii < 2; ++ii) {
        int idx = seg * 512 + ii * 256 + tid;
        float qx = 0.0f, qx2 = 0.0f;
        #pragma unroll
        for (int t = 0; t < SPLIT_; ++t) {
            const float* sl = base + (size_t)t * SLOT_;
            qx  += sl[K_ + idx];
            qx2 += sl[K_ + K_ * D_ + idx];
        }
        qx *= inv_n; qx2 *= inv_n;
        int k = idx >> 6;
        float m = mu[idx];
        float v = var[idx];
        float qsv = qsum_s[k];
        out[(size_t)b * SLOT_ + K_ + idx] = qx - qsv * m;                     // d_mu
        out[(size_t)b * SLOT_ + K_ + K_ * D_ + idx] =
            -qx2 - qsv * m * m + qsv * v + 2.0f * qx * m;                     // d_sigma
    }
}

extern "C" void kernel_launch(void* const* d_in, const int* in_sizes, int n_in,
                              void* d_out, int out_size)
{
    const float* x   = (const float*)d_in[0];
    const float* pi  = (const float*)d_in[1];
    const float* mu  = (const float*)d_in[2];
    const float* var = (const float*)d_in[3];
    float* out = (float*)d_out;

    size_t smem = (size_t)SM_FLOATS * sizeof(float);  // 102,656 bytes -> occ 2
    cudaFuncSetAttribute(fv_main, cudaFuncAttributeMaxDynamicSharedMemorySize, (int)smem);

    dim3 grid(SPLIT_, B_);
    fv_main<<<grid, 256, smem>>>(x, pi, mu, var);
    dim3 g2(B_, 8);
    fv_final<<<g2, 256>>>(pi, mu, var, out);
}

// round 14
// speedup vs baseline: 2.2574x; 2.1426x over previous
#include <cuda_runtime.h>
#include <math.h>

#define B_ 16
#define N_ 16384
#define SPLIT_ 8
#define TILES_ 16
#define SLOT_ (64 + 2*64*64)
#define FULLM 0xffffffffu

typedef unsigned u32; typedef unsigned short u16;

__device__ __align__(16) float g_part[(size_t)B_*SPLIT_*SLOT_];

// strides (bytes)
#define PSTR 144
#define XSTR 144
#define QSTR 272
// shared offsets (bytes)
#define O_IVHH 0
#define O_IVHL 9216
#define O_AAH  18432
#define O_AAL  27648
#define O_XH   36864
#define O_XL   55296
#define O_X2H  73728
#define O_X2L  92160
#define O_QT   110592
#define O_CC   145408
#define O_QP   145664
#define SMEMSZ 147712

__device__ __forceinline__ u32 smem_u32(const void* p){u32 a;asm("{ .reg .u64 t; cvta.to.shared.u64 t, %1; cvt.u32.u64 %0, t; }":"=r"(a):"l"(p));return a;}
__device__ __forceinline__ u16 bf1(float v){u16 h;asm("cvt.rn.bf16.f32 %0, %1;":"=h"(h):"f"(v));return h;}
__device__ __forceinline__ float bff(u16 h){return __uint_as_float(((u32)h)<<16);}
__device__ __forceinline__ u32 PK(u16 lo,u16 hi){return (u32)lo|((u32)hi<<16);}
#define STS16(a,v) asm volatile("st.shared.b16 [%0], %1;"::"r"(a),"h"(v):"memory")
#define STS32(a,v) asm volatile("st.shared.b32 [%0], %1;"::"r"(a),"r"(v):"memory")
#define LDSM4(ad,r0,r1,r2,r3)  asm volatile("ldmatrix.sync.aligned.m8n8.x4.shared.b16 {%0,%1,%2,%3}, [%4];":"=r"(r0),"=r"(r1),"=r"(r2),"=r"(r3):"r"(ad))
#define LDSM4T(ad,r0,r1,r2,r3) asm volatile("ldmatrix.sync.aligned.m8n8.x4.trans.shared.b16 {%0,%1,%2,%3}, [%4];":"=r"(r0),"=r"(r1),"=r"(r2),"=r"(r3):"r"(ad))
#define MMA(c,A0,A1,A2,A3,B0,B1) asm("mma.sync.aligned.m16n8k16.row.col.f32.bf16.bf16.f32 " \
    "{%0,%1,%2,%3}, {%4,%5,%6,%7}, {%8,%9}, {%0,%1,%2,%3};" \
    :"+f"((c)[0]),"+f"((c)[1]),"+f"((c)[2]),"+f"((c)[3]) \
    :"r"(A0),"r"(A1),"r"(A2),"r"(A3),"r"(B0),"r"(B1))

__global__ __launch_bounds__(256,1) void fv_main(
    const float* __restrict__ x, const float* __restrict__ pi,
    const float* __restrict__ mu, const float* __restrict__ var)
{
    extern __shared__ char sm[];
    const u32 sb = smem_u32(sm);
    const int tid = threadIdx.x, wid = tid>>5, lane = tid&31;
    const int b = blockIdx.y, s = blockIdx.x;
    const int tg = lane&3, g = lane>>2;
    const int l15 = lane&15, l7 = lane&7, lh = lane>>4, lq = (lane>>3)&1;
    float* ccs = (float*)(sm + O_CC);

    // ---- stage params: [k][d] bf16 hi/lo for IVH(-0.5/var) and AA(mu/var) ----
    {
        int k = tid>>2, d0 = (tid&3)*16;
        #pragma unroll
        for (int j=0;j<4;++j){
            float4 vv = *(const float4*)(var + k*64 + d0 + 4*j);
            float4 mm = *(const float4*)(mu  + k*64 + d0 + 4*j);
            float i0=1.f/vv.x, i1=1.f/vv.y, i2=1.f/vv.z, i3=1.f/vv.w;
            float h0=-0.5f*i0, h1=-0.5f*i1, h2=-0.5f*i2, h3=-0.5f*i3;
            float a0=mm.x*i0, a1=mm.y*i1, a2=mm.z*i2, a3=mm.w*i3;
            u32 off = (u32)(k*PSTR + (d0+4*j)*2);
            u16 q0=bf1(h0),q1=bf1(h1),q2=bf1(h2),q3=bf1(h3);
            STS32(sb+O_IVHH+off,   PK(q0,q1)); STS32(sb+O_IVHH+off+4, PK(q2,q3));
            STS32(sb+O_IVHL+off,   PK(bf1(h0-bff(q0)),bf1(h1-bff(q1))));
            STS32(sb+O_IVHL+off+4, PK(bf1(h2-bff(q2)),bf1(h3-bff(q3))));
            u16 r0=bf1(a0),r1=bf1(a1),r2=bf1(a2),r3=bf1(a3);
            STS32(sb+O_AAH+off,    PK(r0,r1)); STS32(sb+O_AAH+off+4, PK(r2,r3));
            STS32(sb+O_AAL+off,    PK(bf1(a0-bff(r0)),bf1(a1-bff(r1))));
            STS32(sb+O_AAL+off+4,  PK(bf1(a2-bff(r2)),bf1(a3-bff(r3))));
        }
    }
    if (tid < 64){
        float acc = 0.0f;
        for (int d=0; d<64; ++d){
            float v = var[tid*64+d], m = mu[tid*64+d];
            acc += logf(v) + m*m/v;
        }
        ccs[tid] = logf(pi[tid]) - 0.5f*(64.0f*1.83787706640934548356f + acc);
    }
    __syncthreads();

    float ccr[16];
    #pragma unroll
    for (int i=0;i<16;++i) ccr[i] = ccs[(i>>1)*8 + tg*2 + (i&1)];

    const size_t xoff = ((size_t)b*N_ + (size_t)s*(N_/SPLIT_))*64;
    const float4* xg4 = (const float4*)(x + xoff);

    float4 Pf[8];
    #pragma unroll
    for (int ii=0;ii<8;++ii) Pf[ii] = xg4[tid + 256*ii];

    float acc2[8][2][4];
    #pragma unroll
    for (int m=0;m<8;++m)
        #pragma unroll
        for (int n=0;n<2;++n){acc2[m][n][0]=0;acc2[m][n][1]=0;acc2[m][n][2]=0;acc2[m][n][3]=0;}
    float qacc[16];
    #pragma unroll
    for (int i=0;i<16;++i) qacc[i]=0;

    // precomputed per-thread ldmatrix offsets
    const u32 xa_off = (u32)((16*wid + l15)*XSTR + lh*16);           // phase-1 A
    const u32 pb_off = (u32)((l7 + lh*8)*PSTR + lq*16);              // phase-1 B
    const u32 qa_off = sb + O_QT + (u32)(l15*QSTR + lh*16);          // phase-2 A
    const u32 xb_h = sb + ((wid<4)?O_XH:O_X2H);
    const u32 xb_l = sb + ((wid<4)?O_XL:O_X2L);
    const u32 xb_off = (u32)(l15*XSTR + 32*(wid&3) + lh*16);         // phase-2 B

    for (int tile=0; tile<TILES_; ++tile){
        if (tile) __syncthreads();   // phase-2 of prev tile done before X rewrite
        // ---- stage x tile: hi/lo of x and x^2, [p][d] layout ----
        #pragma unroll
        for (int ii=0;ii<8;++ii){
            int i = tid + 256*ii;
            int row = i>>4, c4 = i&15;
            float4 v = Pf[ii];
            u32 ha = (u32)(row*XSTR + c4*8);
            u16 hx=bf1(v.x),hy=bf1(v.y),hz=bf1(v.z),hw=bf1(v.w);
            STS32(sb+O_XH+ha,   PK(hx,hy)); STS32(sb+O_XH+ha+4, PK(hz,hw));
            STS32(sb+O_XL+ha,   PK(bf1(v.x-bff(hx)),bf1(v.y-bff(hy))));
            STS32(sb+O_XL+ha+4, PK(bf1(v.z-bff(hz)),bf1(v.w-bff(hw))));
            float sx=v.x*v.x, sy=v.y*v.y, sz=v.z*v.z, sw=v.w*v.w;
            u16 ax=bf1(sx),ay=bf1(sy),az=bf1(sz),aw=bf1(sw);
            STS32(sb+O_X2H+ha,   PK(ax,ay)); STS32(sb+O_X2H+ha+4, PK(az,aw));
            STS32(sb+O_X2L+ha,   PK(bf1(sx-bff(ax)),bf1(sy-bff(ay))));
            STS32(sb+O_X2L+ha+4, PK(bf1(sz-bff(az)),bf1(sw-bff(aw))));
        }
        __syncthreads();
        if (tile+1 < TILES_){
            #pragma unroll
            for (int ii=0;ii<8;++ii) Pf[ii] = xg4[(tile+1)*2048 + tid + 256*ii];
        }

        // ---- phase 1: logits, 3-term compensated, C in regs ----
        float c1[8][4];
        #pragma unroll
        for (int i=0;i<8;++i){c1[i][0]=0;c1[i][1]=0;c1[i][2]=0;c1[i][3]=0;}
        #pragma unroll
        for (int ps=0;ps<3;++ps){
            const u32 ab0 = (ps==1)?O_X2L:O_X2H, ab1 = (ps==1)?O_XL:O_XH;
            const u32 bb0 = (ps==2)?O_IVHL:O_IVHH, bb1 = (ps==2)?O_AAL:O_AAH;
            #pragma unroll
            for (int hf=0;hf<2;++hf){
                u32 Ab = sb + (hf?ab1:ab0) + xa_off;
                u32 Bb = sb + (hf?bb1:bb0) + pb_off;
                #pragma unroll
                for (int ks=0;ks<4;++ks){
                    u32 a0,a1,a2,a3; LDSM4(Ab + ks*32, a0,a1,a2,a3);
                    #pragma unroll
                    for (int n2=0;n2<4;++n2){
                        u32 b0,b1,b2,b3; LDSM4(Bb + n2*16*PSTR + ks*32, b0,b1,b2,b3);
                        MMA(c1[n2*2],   a0,a1,a2,a3, b0,b1);
                        MMA(c1[n2*2+1], a0,a1,a2,a3, b2,b3);
                    }
                }
            }
        }

        // ---- softmax (thread holds 2 points x 16 k), Q^T hi/lo to smem ----
        #pragma unroll
        for (int r=0;r<2;++r){
            float mx = -1e30f;
            #pragma unroll
            for (int i=0;i<16;++i){
                float v = c1[i>>1][(r<<1)|(i&1)] + ccr[i];
                c1[i>>1][(r<<1)|(i&1)] = v;
                mx = fmaxf(mx, v);
            }
            mx = fmaxf(mx, __shfl_xor_sync(FULLM, mx, 1));
            mx = fmaxf(mx, __shfl_xor_sync(FULLM, mx, 2));
            float sum = 0.0f;
            #pragma unroll
            for (int i=0;i<16;++i){
                float e = __expf(c1[i>>1][(r<<1)|(i&1)] - mx);
                c1[i>>1][(r<<1)|(i&1)] = e;
                sum += e;
            }
            sum += __shfl_xor_sync(FULLM, sum, 1);
            sum += __shfl_xor_sync(FULLM, sum, 2);
            float inv = __fdividef(1.0f, sum);
            u32 qtb = sb + O_QT + (u32)(tg*544 + (16*wid + g + r*8)*2);
            #pragma unroll
            for (int i=0;i<16;++i){
                float q = c1[i>>1][(r<<1)|(i&1)] * inv;
                qacc[i] += q;
                u16 h = bf1(q);
                u32 koff = (u32)((i>>1)*2176 + (i&1)*272);
                STS16(qtb + koff, h);
                STS16(qtb + koff + 64*272, bf1(q - bff(h)));
            }
        }
        __syncthreads();

        // ---- phase 2: [Qhi;Qlo]^T x [X|X2] hi(+lo for Qhi), acc in regs ----
        #pragma unroll
        for (int ks=0;ks<8;++ks){
            u32 bh0,bh1,bh2,bh3, bl0,bl1,bl2,bl3;
            LDSM4T(xb_h + ks*16*XSTR + xb_off, bh0,bh1,bh2,bh3);
            LDSM4T(xb_l + ks*16*XSTR + xb_off, bl0,bl1,bl2,bl3);
            #pragma unroll
            for (int mt=0;mt<8;++mt){
                u32 a0,a1,a2,a3; LDSM4(qa_off + mt*16*QSTR + ks*32, a0,a1,a2,a3);
                MMA(acc2[mt][0], a0,a1,a2,a3, bh0,bh1);
                MMA(acc2[mt][1], a0,a1,a2,a3, bh2,bh3);
                if (mt<4){
                    MMA(acc2[mt][0], a0,a1,a2,a3, bl0,bl1);
                    MMA(acc2[mt][1], a0,a1,a2,a3, bl2,bl3);
                }
            }
        }
    }

    // ---- Qsum: shuffle-reduce across g, stage per warp, reduce ----
    #pragma unroll
    for (int i=0;i<16;++i){
        qacc[i] += __shfl_xor_sync(FULLM, qacc[i], 4);
        qacc[i] += __shfl_xor_sync(FULLM, qacc[i], 8);
        qacc[i] += __shfl_xor_sync(FULLM, qacc[i], 16);
    }
    float* qp = (float*)(sm + O_QP);
    if (lane < 4){
        #pragma unroll
        for (int i=0;i<16;++i)
            qp[wid*64 + (i>>1)*8 + lane*2 + (i&1)] = qacc[i];
    }
    __syncthreads();

    float* slot = g_part + ((size_t)b*SPLIT_ + s)*SLOT_;
    if (tid < 64){
        float s8 = 0.0f;
        #pragma unroll
        for (int w=0;w<8;++w) s8 += qp[w*64 + tid];
        slot[tid] = s8;
    }
    // ---- write Qx / Qx2 partials (hi rows + lo rows summed) ----
    float* dbase = slot + 64 + ((wid>=4)?4096:0);
    #pragma unroll
    for (int mt=0;mt<4;++mt){
        #pragma unroll
        for (int nt=0;nt<2;++nt){
            int k0 = mt*16 + g;
            int dc = 16*(wid&3) + nt*8 + tg*2;
            float2 v;
            v.x = acc2[mt][nt][0] + acc2[mt+4][nt][0];
            v.y = acc2[mt][nt][1] + acc2[mt+4][nt][1];
            *(float2*)(dbase + k0*64 + dc) = v;
            v.x = acc2[mt][nt][2] + acc2[mt+4][nt][2];
            v.y = acc2[mt][nt][3] + acc2[mt+4][nt][3];
            *(float2*)(dbase + (k0+8)*64 + dc) = v;
        }
    }
}

__global__ __launch_bounds__(256) void fv_final(
    const float* __restrict__ pi, const float* __restrict__ mu,
    const float* __restrict__ var, float* __restrict__ out)
{
    const int b = blockIdx.x, seg = blockIdx.y, tid = threadIdx.x;
    __shared__ float qsum_s[64];
    const float* base = g_part + (size_t)b*SPLIT_*SLOT_;
    const float inv_n = 1.0f/(float)N_;
    if (tid < 64){
        float ssum = 0.0f;
        #pragma unroll
        for (int t=0;t<SPLIT_;++t) ssum += base[(size_t)t*SLOT_ + tid];
        ssum *= inv_n;
        qsum_s[tid] = ssum;
        if (seg==0) out[(size_t)b*SLOT_ + tid] = ssum - pi[tid];
    }
    __syncthreads();
    #pragma unroll
    for (int ii=0; ii<2; ++ii){
        int idx = seg*512 + ii*256 + tid;
        float qx=0.0f, qx2=0.0f;
        #pragma unroll
        for (int t=0;t<SPLIT_;++t){
            const float* sl = base + (size_t)t*SLOT_;
            qx  += sl[64 + idx];
            qx2 += sl[64 + 64*64 + idx];
        }
        qx *= inv_n; qx2 *= inv_n;
        float m = mu[idx], v = var[idx], qsv = qsum_s[idx>>6];
        out[(size_t)b*SLOT_ + 64 + idx] = qx - qsv*m;
        out[(size_t)b*SLOT_ + 64 + 64*64 + idx] = -qx2 - qsv*m*m + qsv*v + 2.0f*qx*m;
    }
}

extern "C" void kernel_launch(void* const* d_in, const int* in_sizes, int n_in,
                              void* d_out, int out_size)
{
    const float* x   = (const float*)d_in[0];
    const float* pi  = (const float*)d_in[1];
    const float* mu  = (const float*)d_in[2];
    const float* var = (const float*)d_in[3];
    float* out = (float*)d_out;
    cudaFuncSetAttribute(fv_main, cudaFuncAttributeMaxDynamicSharedMemorySize, SMEMSZ);
    dim3 grid(SPLIT_, B_);
    fv_main<<<grid, 256, SMEMSZ>>>(x, pi, mu, var);
    dim3 g2(B_, 8);
    fv_final<<<g2, 256>>>(pi, mu, var, out);
}

// round 15
// speedup vs baseline: 2.9549x; 1.3090x over previous
#include <cuda_runtime.h>
#include <math.h>

#define B_ 16
#define N_ 16384
#define SPLIT_ 8
#define TILES_ 16
#define SLOT_ (64 + 2*64*64)
#define FULLM 0xffffffffu

typedef unsigned u32; typedef unsigned short u16;

__device__ __align__(16) float g_part[(size_t)B_*SPLIT_*SLOT_];

// strides (bytes)
#define PSTR 144
#define XSTR 144
#define QSTR 272
// shared offsets (bytes)
#define O_IVHH 0
#define O_IVHL 9216
#define O_AAH  18432
#define O_AAL  27648
#define O_XA   36864          /* X buffer A: XH,XL,X2H,X2L each 18432 */
#define O_XB   110592         /* X buffer B */
#define O_QT   184320         /* Q tile [p][k-hi 128B | k-lo 128B] */
#define O_CC   219136
#define O_QP   219392
#define SMEMSZ 221440

__device__ __forceinline__ u32 smem_u32(const void* p){u32 a;asm("{ .reg .u64 t; cvta.to.shared.u64 t, %1; cvt.u32.u64 %0, t; }":"=r"(a):"l"(p));return a;}
// pack: lo16 = bf16(a), hi16 = bf16(b)
__device__ __forceinline__ u32 cvt2(float b, float a){u32 r;asm("cvt.rn.satfinite.bf16x2.f32 %0, %1, %2;":"=r"(r):"f"(b),"f"(a));return r;}
__device__ __forceinline__ float hil(u32 h){return __uint_as_float(h<<16);}        // value of lo16 part
__device__ __forceinline__ float hih(u32 h){return __uint_as_float(h&0xffff0000u);}// value of hi16 part
#define STS32(a,v) asm volatile("st.shared.b32 [%0], %1;"::"r"(a),"r"(v):"memory")
#define STS64(a,v0,v1) asm volatile("st.shared.v2.b32 [%0], {%1,%2};"::"r"(a),"r"(v0),"r"(v1):"memory")
#define LDSM4(ad,r0,r1,r2,r3)  asm volatile("ldmatrix.sync.aligned.m8n8.x4.shared.b16 {%0,%1,%2,%3}, [%4];":"=r"(r0),"=r"(r1),"=r"(r2),"=r"(r3):"r"(ad))
#define LDSM4T(ad,r0,r1,r2,r3) asm volatile("ldmatrix.sync.aligned.m8n8.x4.trans.shared.b16 {%0,%1,%2,%3}, [%4];":"=r"(r0),"=r"(r1),"=r"(r2),"=r"(r3):"r"(ad))
#define MMA(c,A0,A1,A2,A3,B0,B1) asm("mma.sync.aligned.m16n8k16.row.col.f32.bf16.bf16.f32 " \
    "{%0,%1,%2,%3}, {%4,%5,%6,%7}, {%8,%9}, {%0,%1,%2,%3};" \
    :"+f"((c)[0]),"+f"((c)[1]),"+f"((c)[2]),"+f"((c)[3]) \
    :"r"(A0),"r"(A1),"r"(A2),"r"(A3),"r"(B0),"r"(B1))

__global__ __launch_bounds__(256,1) void fv_main(
    const float* __restrict__ x, const float* __restrict__ pi,
    const float* __restrict__ mu, const float* __restrict__ var)
{
    extern __shared__ char sm[];
    const u32 sb = smem_u32(sm);
    const int tid = threadIdx.x, wid = tid>>5, lane = tid&31;
    const int b = blockIdx.y, s = blockIdx.x;
    const int tg = lane&3, g = lane>>2;
    const int l15 = lane&15, l7 = lane&7, lh = lane>>4, lq = (lane>>3)&1;
    float* ccs = (float*)(sm + O_CC);

    const size_t xoff = ((size_t)b*N_ + (size_t)s*(N_/SPLIT_))*64;
    const float4* xg4 = (const float4*)(x + xoff);

    // prologue LDG for tile 0
    float4 Pf[8];
    #pragma unroll
    for (int ii=0;ii<8;++ii) Pf[ii] = xg4[tid + 256*ii];

    // ---- stage params: [k][d] bf16 hi/lo for IVH(-0.5/var) and AA(mu/var) ----
    {
        int k = tid>>2, d0 = (tid&3)*16;
        #pragma unroll
        for (int j=0;j<4;++j){
            float4 vv = *(const float4*)(var + k*64 + d0 + 4*j);
            float4 mm = *(const float4*)(mu  + k*64 + d0 + 4*j);
            float i0=1.f/vv.x, i1=1.f/vv.y, i2=1.f/vv.z, i3=1.f/vv.w;
            float h0=-0.5f*i0, h1=-0.5f*i1, h2=-0.5f*i2, h3=-0.5f*i3;
            float a0=mm.x*i0, a1=mm.y*i1, a2=mm.z*i2, a3=mm.w*i3;
            u32 off = (u32)(k*PSTR + (d0+4*j)*2);
            u32 p01=cvt2(h1,h0), p23=cvt2(h3,h2);
            STS64(sb+O_IVHH+off, p01, p23);
            STS64(sb+O_IVHL+off, cvt2(h1-hih(p01),h0-hil(p01)), cvt2(h3-hih(p23),h2-hil(p23)));
            u32 q01=cvt2(a1,a0), q23=cvt2(a3,a2);
            STS64(sb+O_AAH+off, q01, q23);
            STS64(sb+O_AAL+off, cvt2(a1-hih(q01),a0-hil(q01)), cvt2(a3-hih(q23),a2-hil(q23)));
        }
    }
    if (tid < 64){
        float acc = 0.0f;
        for (int d=0; d<64; ++d){
            float v = var[tid*64+d], m = mu[tid*64+d];
            acc += logf(v) + m*m/v;
        }
        ccs[tid] = logf(pi[tid]) - 0.5f*(64.0f*1.83787706640934548356f + acc);
    }

    // ---- stage tile 0 into buffer A ----
    #pragma unroll
    for (int ii=0;ii<8;++ii){
        int i = tid + 256*ii;
        u32 ha = (u32)((i>>4)*XSTR + (i&15)*8);
        float4 v = Pf[ii];
        u32 h01=cvt2(v.y,v.x), h23=cvt2(v.w,v.z);
        STS64(sb+O_XA+ha, h01, h23);
        STS64(sb+O_XA+18432+ha, cvt2(v.y-hih(h01),v.x-hil(h01)), cvt2(v.w-hih(h23),v.z-hil(h23)));
        float sx=v.x*v.x, sy=v.y*v.y, sz=v.z*v.z, sw=v.w*v.w;
        u32 s01=cvt2(sy,sx), s23=cvt2(sw,sz);
        STS64(sb+O_XA+36864+ha, s01, s23);
        STS64(sb+O_XA+55296+ha, cvt2(sy-hih(s01),sx-hil(s01)), cvt2(sw-hih(s23),sz-hil(s23)));
    }
    // prologue LDG for tile 1
    #pragma unroll
    for (int ii=0;ii<8;++ii) Pf[ii] = xg4[2048 + tid + 256*ii];
    __syncthreads();

    float ccr[16];
    #pragma unroll
    for (int i=0;i<16;++i) ccr[i] = ccs[(i>>1)*8 + tg*2 + (i&1)];

    float acc2[8][2][4];
    #pragma unroll
    for (int m=0;m<8;++m)
        #pragma unroll
        for (int n=0;n<2;++n){acc2[m][n][0]=0;acc2[m][n][1]=0;acc2[m][n][2]=0;acc2[m][n][3]=0;}
    float qacc[16];
    #pragma unroll
    for (int i=0;i<16;++i) qacc[i]=0;

    // per-thread ldmatrix offsets
    const u32 xa_off = (u32)((16*wid + l15)*XSTR + lh*16);               // phase-1 A (non-trans)
    const u32 pb_off = (u32)((l7 + lh*8)*PSTR + lq*16);                  // phase-1 B (non-trans)
    const u32 qa_off = sb + O_QT + (u32)((l7 + lh*8)*QSTR + lq*16);      // phase-2 A (trans)
    const u32 xb_off = (u32)(l15*XSTR + 32*(wid&3) + lh*16);             // phase-2 B (trans)
    const u32 x2sel = (wid<4)? 0u : 36864u;

    for (int tile=0; tile<TILES_; ++tile){
        const u32 bufC = sb + ((tile&1)? O_XB : O_XA);
        const u32 bufN = sb + ((tile&1)? O_XA : O_XB);

        // ---- phase 1: logits, 3-term compensated, B-fragments reused across hi/lo A ----
        float c1[8][4];
        #pragma unroll
        for (int i=0;i<8;++i){c1[i][0]=0;c1[i][1]=0;c1[i][2]=0;c1[i][3]=0;}
        #pragma unroll
        for (int ch=0; ch<2; ++ch){
            const u32 Ah = bufC + (ch? 0u : 36864u) + xa_off;  // ch0: X2, ch1: X
            const u32 Al = Ah + 18432u;
            const u32 Bh = sb + (ch? O_AAH : O_IVHH) + pb_off;
            const u32 Bl = Bh + 9216u;
            #pragma unroll
            for (int ks=0; ks<4; ++ks){
                u32 a0,a1,a2,a3, e0,e1,e2,e3;
                LDSM4(Ah + ks*32, a0,a1,a2,a3);
                LDSM4(Al + ks*32, e0,e1,e2,e3);
                #pragma unroll
                for (int n2=0;n2<4;++n2){
                    u32 b0,b1,b2,b3; LDSM4(Bh + n2*16*PSTR + ks*32, b0,b1,b2,b3);
                    MMA(c1[2*n2],   a0,a1,a2,a3, b0,b1);
                    MMA(c1[2*n2+1], a0,a1,a2,a3, b2,b3);
                    MMA(c1[2*n2],   e0,e1,e2,e3, b0,b1);
                    MMA(c1[2*n2+1], e0,e1,e2,e3, b2,b3);
                }
                #pragma unroll
                for (int n2=0;n2<4;++n2){
                    u32 b0,b1,b2,b3; LDSM4(Bl + n2*16*PSTR + ks*32, b0,b1,b2,b3);
                    MMA(c1[2*n2],   a0,a1,a2,a3, b0,b1);
                    MMA(c1[2*n2+1], a0,a1,a2,a3, b2,b3);
                }
            }
        }

        // ---- softmax: thread holds 2 points x 16 k; results kept in c1 ----
        #pragma unroll
        for (int r=0;r<2;++r){
            float v[16];
            #pragma unroll
            for (int i=0;i<16;++i) v[i] = c1[i>>1][(r<<1)|(i&1)] + ccr[i];
            float m0=fmaxf(v[0],v[1]), m1=fmaxf(v[2],v[3]), m2=fmaxf(v[4],v[5]), m3=fmaxf(v[6],v[7]);
            float m4=fmaxf(v[8],v[9]), m5=fmaxf(v[10],v[11]), m6=fmaxf(v[12],v[13]), m7=fmaxf(v[14],v[15]);
            float mx = fmaxf(fmaxf(fmaxf(m0,m1),fmaxf(m2,m3)), fmaxf(fmaxf(m4,m5),fmaxf(m6,m7)));
            mx = fmaxf(mx, __shfl_xor_sync(FULLM, mx, 1));
            mx = fmaxf(mx, __shfl_xor_sync(FULLM, mx, 2));
            #pragma unroll
            for (int i=0;i<16;++i) v[i] = __expf(v[i] - mx);
            float s0=v[0]+v[1], s1=v[2]+v[3], s2=v[4]+v[5], s3=v[6]+v[7];
            float s4=v[8]+v[9], s5=v[10]+v[11], s6=v[12]+v[13], s7=v[14]+v[15];
            float sum = ((s0+s1)+(s2+s3)) + ((s4+s5)+(s6+s7));
            sum += __shfl_xor_sync(FULLM, sum, 1);
            sum += __shfl_xor_sync(FULLM, sum, 2);
            float inv = __fdividef(1.0f, sum);
            #pragma unroll
            for (int i=0;i<16;++i){
                float q = v[i]*inv;
                qacc[i] += q;
                c1[i>>1][(r<<1)|(i&1)] = q;
            }
        }

        __syncthreads();   // phase-2(t-1) done reading QT / this-tile X buffers settled

        // ---- stage next tile into the other buffer ----
        if (tile+1 < TILES_){
            #pragma unroll
            for (int ii=0;ii<8;++ii){
                int i = tid + 256*ii;
                u32 ha = (u32)((i>>4)*XSTR + (i&15)*8);
                float4 v = Pf[ii];
                u32 h01=cvt2(v.y,v.x), h23=cvt2(v.w,v.z);
                STS64(bufN+ha, h01, h23);
                STS64(bufN+18432+ha, cvt2(v.y-hih(h01),v.x-hil(h01)), cvt2(v.w-hih(h23),v.z-hil(h23)));
                float sx=v.x*v.x, sy=v.y*v.y, sz=v.z*v.z, sw=v.w*v.w;
                u32 s01=cvt2(sy,sx), s23=cvt2(sw,sz);
                STS64(bufN+36864+ha, s01, s23);
                STS64(bufN+55296+ha, cvt2(sy-hih(s01),sx-hil(s01)), cvt2(sw-hih(s23),sz-hil(s23)));
            }
        }
        // ---- Q store: [p][k] rows, hi at +0, lo at +128 ----
        #pragma unroll
        for (int r=0;r<2;++r){
            u32 qrow = sb + O_QT + (u32)((16*wid + g + 8*r)*QSTR + tg*4);
            #pragma unroll
            for (int j=0;j<8;++j){
                float qe = c1[j][(r<<1)], qo = c1[j][(r<<1)|1];
                u32 h = cvt2(qo, qe);
                STS32(qrow + j*16, h);
                STS32(qrow + 128 + j*16, cvt2(qo-hih(h), qe-hil(h)));
            }
        }
        // LDG for tile t+2
        if (tile+2 < TILES_){
            #pragma unroll
            for (int ii=0;ii<8;++ii) Pf[ii] = xg4[(tile+2)*2048 + tid + 256*ii];
        }
        __syncthreads();   // QT + next X buffer published

        // ---- phase 2: A = Q^T via trans-ldsm on [p][k]; B = X/X2 via trans-ldsm ----
        const u32 xbh = bufC + x2sel + xb_off;
        const u32 xbl = xbh + 18432u;
        #pragma unroll
        for (int ks=0;ks<8;++ks){
            u32 bh0,bh1,bh2,bh3, bl0,bl1,bl2,bl3;
            LDSM4T(xbh + ks*16*XSTR, bh0,bh1,bh2,bh3);
            LDSM4T(xbl + ks*16*XSTR, bl0,bl1,bl2,bl3);
            #pragma unroll
            for (int mt=0;mt<8;++mt){
                u32 col = (mt<4)? (u32)(mt*32) : (u32)(128 + (mt-4)*32);
                u32 a0,a1,a2,a3;
                LDSM4T(qa_off + ks*16*QSTR + col, a0,a1,a2,a3);
                MMA(acc2[mt][0], a0,a1,a2,a3, bh0,bh1);
                MMA(acc2[mt][1], a0,a1,a2,a3, bh2,bh3);
                if (mt<4){
                    MMA(acc2[mt][0], a0,a1,a2,a3, bl0,bl1);
                    MMA(acc2[mt][1], a0,a1,a2,a3, bl2,bl3);
                }
            }
        }
    }

    // ---- Qsum: shuffle-reduce across g, stage per warp, reduce ----
    #pragma unroll
    for (int i=0;i<16;++i){
        qacc[i] += __shfl_xor_sync(FULLM, qacc[i], 4);
        qacc[i] += __shfl_xor_sync(FULLM, qacc[i], 8);
        qacc[i] += __shfl_xor_sync(FULLM, qacc[i], 16);
    }
    float* qp = (float*)(sm + O_QP);
    if (lane < 4){
        #pragma unroll
        for (int i=0;i<16;++i)
            qp[wid*64 + (i>>1)*8 + lane*2 + (i&1)] = qacc[i];
    }
    __syncthreads();

    float* slot = g_part + ((size_t)b*SPLIT_ + s)*SLOT_;
    if (tid < 64){
        float s8 = 0.0f;
        #pragma unroll
        for (int w=0;w<8;++w) s8 += qp[w*64 + tid];
        slot[tid] = s8;
    }
    // ---- write Qx / Qx2 partials (Qhi rows + Qlo rows summed) ----
    float* dbase = slot + 64 + ((wid>=4)?4096:0);
    #pragma unroll
    for (int mt=0;mt<4;++mt){
        #pragma unroll
        for (int nt=0;nt<2;++nt){
            int k0 = mt*16 + g;
            int dc = 16*(wid&3) + nt*8 + tg*2;
            float2 v;
            v.x = acc2[mt][nt][0] + acc2[mt+4][nt][0];
            v.y = acc2[mt][nt][1] + acc2[mt+4][nt][1];
            *(float2*)(dbase + k0*64 + dc) = v;
            v.x = acc2[mt][nt][2] + acc2[mt+4][nt][2];
            v.y = acc2[mt][nt][3] + acc2[mt+4][nt][3];
            *(float2*)(dbase + (k0+8)*64 + dc) = v;
        }
    }
}

__global__ __launch_bounds__(256) void fv_final(
    const float* __restrict__ pi, const float* __restrict__ mu,
    const float* __restrict__ var, float* __restrict__ out)
{
    const int b = blockIdx.x, seg = blockIdx.y, tid = threadIdx.x;
    __shared__ float qsum_s[64];
    const float* base = g_part + (size_t)b*SPLIT_*SLOT_;
    const float inv_n = 1.0f/(float)N_;
    if (tid < 64){
        float ssum = 0.0f;
        #pragma unroll
        for (int t=0;t<SPLIT_;++t) ssum += base[(size_t)t*SLOT_ + tid];
        ssum *= inv_n;
        qsum_s[tid] = ssum;
        if (seg==0) out[(size_t)b*SLOT_ + tid] = ssum - pi[tid];
    }
    __syncthreads();
    {
        int idx = seg*256 + tid;
        float qx=0.0f, qx2=0.0f;
        #pragma unroll
        for (int t=0;t<SPLIT_;++t){
            const float* sl = base + (size_t)t*SLOT_;
            qx  += sl[64 + idx];
            qx2 += sl[64 + 64*64 + idx];
        }
        qx *= inv_n; qx2 *= inv_n;
        float m = mu[idx], v = var[idx], qsv = qsum_s[idx>>6];
        out[(size_t)b*SLOT_ + 64 + idx] = qx - qsv*m;
        out[(size_t)b*SLOT_ + 64 + 64*64 + idx] = -qx2 - qsv*m*m + qsv*v + 2.0f*qx*m;
    }
}

extern "C" void kernel_launch(void* const* d_in, const int* in_sizes, int n_in,
                              void* d_out, int out_size)
{
    const float* x   = (const float*)d_in[0];
    const float* pi  = (const float*)d_in[1];
    const float* mu  = (const float*)d_in[2];
    const float* var = (const float*)d_in[3];
    float* out = (float*)d_out;
    cudaFuncSetAttribute(fv_main, cudaFuncAttributeMaxDynamicSharedMemorySize, SMEMSZ);
    dim3 grid(SPLIT_, B_);
    fv_main<<<grid, 256, SMEMSZ>>>(x, pi, mu, var);
    dim3 g2(B_, 16);
    fv_final<<<g2, 256>>>(pi, mu, var, out);
}